// round 6
// baseline (speedup 1.0000x reference)
#include <cuda_runtime.h>

#define N_USER   100000
#define N_ITEM   100000
#define N_NODE2  200000          // combined dst space: [0,100K)=item(u2i), [100K,200K)=user(i2u)
#define N_EDGE   1600000
#define N_EDGE2  3200000
#define IN_DIM   128
#define OUT_DIM  64
#define NEG_SLOPE 0.01f
#define LROWS    32
#define NBLK_SCAN 196            // ceil(200000/1024)

// ---------------- device scratch (static, no runtime alloc) ----------------
__device__ float  g_Wh_user[(size_t)N_USER * OUT_DIM];   // 25.6 MB
__device__ float  g_Wh_item[(size_t)N_ITEM * OUT_DIM];   // 25.6 MB
__device__ float  g_su_src[N_USER];
__device__ float  g_su_dst[N_USER];
__device__ float  g_si_src[N_ITEM];
__device__ float  g_si_dst[N_ITEM];
__device__ int    g_cnt[N_NODE2];
__device__ int    g_offs[N_NODE2];
__device__ int    g_cursor[N_NODE2];
__device__ int    g_bsum[NBLK_SCAN];
__device__ int    g_boff[NBLK_SCAN];
__device__ float2 g_csr[N_EDGE2];     // packed (src_as_float, ex), 25.6 MB

// ---------------- per-replay reset: degree counters ----------------
__global__ __launch_bounds__(256) void zero_kernel(int* __restrict__ cnt)
{
    int i = blockIdx.x * blockDim.x + threadIdx.x;
    if (i < N_NODE2) cnt[i] = 0;
}

// ------- Wh = feat @ W + b fused with s_src/s_dst epilogue -------
// 32 rows/block, 256 threads: thread = (cq in [0,16): 4 cols, rg in [0,16): 2 rows)
__global__ __launch_bounds__(256) void linear_attn_kernel(
    const float* __restrict__ feat, const float* __restrict__ W,
    const float* __restrict__ b, const float* __restrict__ attn,
    float* __restrict__ Wh, float* __restrict__ s_src, float* __restrict__ s_dst)
{
    __shared__ float Ws[IN_DIM * OUT_DIM];   // 32 KB
    __shared__ float fs[LROWS][IN_DIM];      // 16 KB (reused for Wh tile)
    int tid = threadIdx.x;

    #pragma unroll
    for (int i = tid; i < IN_DIM * OUT_DIM; i += 256) Ws[i] = W[i];

    int row0 = blockIdx.x * LROWS;
    const float4* fsrc = reinterpret_cast<const float4*>(feat + (size_t)row0 * IN_DIM);
    float4* fdst = reinterpret_cast<float4*>(&fs[0][0]);
    #pragma unroll
    for (int i = tid; i < LROWS * IN_DIM / 4; i += 256) fdst[i] = fsrc[i];
    __syncthreads();

    int cq = tid & 15;   // column quad (4 cols)
    int rg = tid >> 4;   // row group (2 rows)
    const float4* Ws4 = reinterpret_cast<const float4*>(Ws);
    float4 accA = {0.f,0.f,0.f,0.f}, accB = {0.f,0.f,0.f,0.f};
    const float4* fA4 = reinterpret_cast<const float4*>(&fs[rg * 2 + 0][0]);
    const float4* fB4 = reinterpret_cast<const float4*>(&fs[rg * 2 + 1][0]);

    #pragma unroll 4
    for (int k4 = 0; k4 < IN_DIM / 4; k4++) {
        float4 w0 = Ws4[(k4 * 4 + 0) * 16 + cq];
        float4 w1 = Ws4[(k4 * 4 + 1) * 16 + cq];
        float4 w2 = Ws4[(k4 * 4 + 2) * 16 + cq];
        float4 w3 = Ws4[(k4 * 4 + 3) * 16 + cq];
        float4 fA = fA4[k4];
        float4 fB = fB4[k4];
        accA.x = fmaf(fA.x, w0.x, accA.x); accA.y = fmaf(fA.x, w0.y, accA.y);
        accA.z = fmaf(fA.x, w0.z, accA.z); accA.w = fmaf(fA.x, w0.w, accA.w);
        accA.x = fmaf(fA.y, w1.x, accA.x); accA.y = fmaf(fA.y, w1.y, accA.y);
        accA.z = fmaf(fA.y, w1.z, accA.z); accA.w = fmaf(fA.y, w1.w, accA.w);
        accA.x = fmaf(fA.z, w2.x, accA.x); accA.y = fmaf(fA.z, w2.y, accA.y);
        accA.z = fmaf(fA.z, w2.z, accA.z); accA.w = fmaf(fA.z, w2.w, accA.w);
        accA.x = fmaf(fA.w, w3.x, accA.x); accA.y = fmaf(fA.w, w3.y, accA.y);
        accA.z = fmaf(fA.w, w3.z, accA.z); accA.w = fmaf(fA.w, w3.w, accA.w);
        accB.x = fmaf(fB.x, w0.x, accB.x); accB.y = fmaf(fB.x, w0.y, accB.y);
        accB.z = fmaf(fB.x, w0.z, accB.z); accB.w = fmaf(fB.x, w0.w, accB.w);
        accB.x = fmaf(fB.y, w1.x, accB.x); accB.y = fmaf(fB.y, w1.y, accB.y);
        accB.z = fmaf(fB.y, w1.z, accB.z); accB.w = fmaf(fB.y, w1.w, accB.w);
        accB.x = fmaf(fB.z, w2.x, accB.x); accB.y = fmaf(fB.z, w2.y, accB.y);
        accB.z = fmaf(fB.z, w2.z, accB.z); accB.w = fmaf(fB.z, w2.w, accB.w);
        accB.x = fmaf(fB.w, w3.x, accB.x); accB.y = fmaf(fB.w, w3.y, accB.y);
        accB.z = fmaf(fB.w, w3.z, accB.z); accB.w = fmaf(fB.w, w3.w, accB.w);
    }

    float4 b4 = reinterpret_cast<const float4*>(b)[cq];
    accA.x += b4.x; accA.y += b4.y; accA.z += b4.z; accA.w += b4.w;
    accB.x += b4.x; accB.y += b4.y; accB.z += b4.z; accB.w += b4.w;

    int rA = rg * 2, rB = rg * 2 + 1;
    float4* Wh4 = reinterpret_cast<float4*>(Wh);
    Wh4[(size_t)(row0 + rA) * 16 + cq] = accA;
    Wh4[(size_t)(row0 + rB) * 16 + cq] = accB;

    __syncthreads();   // done reading fs; reuse as Wh tile [32][64]
    float4* sWh4 = reinterpret_cast<float4*>(&fs[0][0]);
    sWh4[rA * 16 + cq] = accA;
    sWh4[rB * 16 + cq] = accB;
    __syncthreads();

    // epilogue: 8 warps x 4 rows
    int wid = tid >> 5, lane = tid & 31;
    float a0 = attn[lane],      a1 = attn[lane + 32];
    float c0 = attn[64 + lane], c1 = attn[96 + lane];
    const float* sWh = &fs[0][0];
    #pragma unroll
    for (int rr = 0; rr < 4; rr++) {
        int row = wid * 4 + rr;
        float v0 = sWh[row * 64 + lane];
        float v1 = sWh[row * 64 + lane + 32];
        float ps = fmaf(v0, a0, v1 * a1);
        float pd = fmaf(v0, c0, v1 * c1);
        #pragma unroll
        for (int o = 16; o; o >>= 1) {
            ps += __shfl_xor_sync(0xffffffffu, ps, o);
            pd += __shfl_xor_sync(0xffffffffu, pd, o);
        }
        if (lane == 0) { s_src[row0 + row] = ps; s_dst[row0 + row] = pd; }
    }
}

// ---------------- histogram of dst degrees, both etypes (4 edges/thread) ----
__global__ __launch_bounds__(256) void hist_kernel(const int4* __restrict__ dstA4,
                                                   const int4* __restrict__ dstB4,
                                                   int* __restrict__ cnt)
{
    int i = blockIdx.x * blockDim.x + threadIdx.x;
    const int nq = N_EDGE / 4;
    if (i >= 2 * nq) return;
    bool second = i >= nq;
    int4 d = second ? dstB4[i - nq] : dstA4[i];
    int gbase = second ? N_ITEM : 0;
    atomicAdd(&cnt[gbase + d.x], 1);
    atomicAdd(&cnt[gbase + d.y], 1);
    atomicAdd(&cnt[gbase + d.z], 1);
    atomicAdd(&cnt[gbase + d.w], 1);
}

// ---------------- exclusive scan (3 kernels) ----------------
__global__ __launch_bounds__(256) void scan1_kernel(const int* __restrict__ cnt,
        int* __restrict__ offs, int* __restrict__ bsum)
{
    __shared__ int wsum[8];
    int tid = threadIdx.x;
    int base = blockIdx.x * 1024 + tid * 4;
    int v[4];
    #pragma unroll
    for (int q = 0; q < 4; q++) { int i = base + q; v[q] = (i < N_NODE2) ? cnt[i] : 0; }
    int t = v[0] + v[1] + v[2] + v[3];
    int lane = tid & 31, wid = tid >> 5;
    int inc = t;
    #pragma unroll
    for (int o = 1; o < 32; o <<= 1) { int n = __shfl_up_sync(0xffffffffu, inc, o); if (lane >= o) inc += n; }
    if (lane == 31) wsum[wid] = inc;
    __syncthreads();
    if (wid == 0) {
        int ws = (lane < 8) ? wsum[lane] : 0;
        int winc = ws;
        #pragma unroll
        for (int o = 1; o < 8; o <<= 1) { int n = __shfl_up_sync(0xffffffffu, winc, o); if (lane >= o) winc += n; }
        if (lane < 8) wsum[lane] = winc - ws;          // exclusive warp offsets
        if (lane == 7) bsum[blockIdx.x] = winc;        // block total
    }
    __syncthreads();
    int run = wsum[wid] + (inc - t);
    #pragma unroll
    for (int q = 0; q < 4; q++) { int i = base + q; if (i < N_NODE2) offs[i] = run; run += v[q]; }
}

__global__ __launch_bounds__(256) void scan2_kernel(const int* __restrict__ bsum,
                                                    int* __restrict__ boff)
{
    __shared__ int wsum[8];
    int tid = threadIdx.x;
    int v = (tid < NBLK_SCAN) ? bsum[tid] : 0;
    int lane = tid & 31, wid = tid >> 5;
    int inc = v;
    #pragma unroll
    for (int o = 1; o < 32; o <<= 1) { int n = __shfl_up_sync(0xffffffffu, inc, o); if (lane >= o) inc += n; }
    if (lane == 31) wsum[wid] = inc;
    __syncthreads();
    if (wid == 0) {
        int ws = (lane < 8) ? wsum[lane] : 0;
        int winc = ws;
        #pragma unroll
        for (int o = 1; o < 8; o <<= 1) { int n = __shfl_up_sync(0xffffffffu, winc, o); if (lane >= o) winc += n; }
        if (lane < 8) wsum[lane] = winc - ws;
    }
    __syncthreads();
    if (tid < NBLK_SCAN) boff[tid] = wsum[wid] + (inc - v);
}

__global__ __launch_bounds__(256) void scan3_kernel(int* __restrict__ offs,
        const int* __restrict__ boff, int* __restrict__ cursor)
{
    int i = blockIdx.x * blockDim.x + threadIdx.x;
    if (i >= N_NODE2) return;
    int o = offs[i] + boff[i >> 10];
    offs[i] = o;
    cursor[i] = o;
}

// --------- scatter (both etypes): ex = exp(lrelu(e)); csr[pos] = (src, ex) ---------
__global__ __launch_bounds__(256) void scatter_kernel(
    const int* __restrict__ srcA, const int* __restrict__ dstA,
    const int* __restrict__ srcB, const int* __restrict__ dstB,
    const float* __restrict__ su_src, const float* __restrict__ su_dst,
    const float* __restrict__ si_src, const float* __restrict__ si_dst,
    int* __restrict__ cursor, float2* __restrict__ csr)
{
    int t = blockIdx.x * blockDim.x + threadIdx.x;
    if (t >= N_EDGE2) return;
    bool second = t >= N_EDGE;
    int e = second ? t - N_EDGE : t;
    int s = second ? srcB[e] : srcA[e];
    int d = second ? dstB[e] : dstA[e];
    float vs = second ? si_src[s] : su_src[s];
    float vd = second ? su_dst[d] : si_dst[d];
    float v = vs + vd;
    v = v > 0.f ? v : NEG_SLOPE * v;
    float ex = __expf(v);
    int gd = (second ? N_ITEM : 0) + d;
    int pos = atomicAdd(&cursor[gd], 1);
    csr[pos] = make_float2(__int_as_float(s), ex);
}

// --------- aggregate: warp per dst node; denominator computed in-loop ---------
__global__ __launch_bounds__(256) void agg_kernel(
    const int* __restrict__ offs, const float2* __restrict__ csr,
    const float2* __restrict__ Whu2, const float2* __restrict__ Whi2,
    float2* __restrict__ out2)
{
    int g = (blockIdx.x * 256 + threadIdx.x) >> 5;
    int lane = threadIdx.x & 31;
    if (g >= N_NODE2) return;

    int beg = offs[g];
    int end = (g == N_NODE2 - 1) ? N_EDGE2 : offs[g + 1];
    const float2* Wh2 = (g < N_ITEM) ? Whu2 : Whi2;            // item-dst <- user src
    int orow = (g < N_ITEM) ? (N_USER + g) : (g - N_ITEM);

    float2 acc = make_float2(0.f, 0.f);
    float den = 0.f;

    int nfull = (end - beg) >> 5;
    int k = beg + lane;
    for (int c = 0; c < nfull; c++, k += 32) {
        float2 p = csr[k];
        int   s  = __float_as_int(p.x);
        float ex = p.y;
        #pragma unroll 8
        for (int j = 0; j < 32; j++) {
            int   sj = __shfl_sync(0xffffffffu, s,  j);
            float ej = __shfl_sync(0xffffffffu, ex, j);
            float2 z = Wh2[(size_t)sj * 32 + lane];
            acc.x = fmaf(ej, z.x, acc.x);
            acc.y = fmaf(ej, z.y, acc.y);
            den += ej;
        }
    }
    int rem = (end - beg) & 31;
    if (rem) {
        int   s = 0; float ex = 0.f;
        if (lane < rem) { float2 p = csr[k]; s = __float_as_int(p.x); ex = p.y; }
        for (int j = 0; j < rem; j++) {
            int   sj = __shfl_sync(0xffffffffu, s,  j);
            float ej = __shfl_sync(0xffffffffu, ex, j);
            float2 z = Wh2[(size_t)sj * 32 + lane];
            acc.x = fmaf(ej, z.x, acc.x);
            acc.y = fmaf(ej, z.y, acc.y);
            den += ej;
        }
    }
    if (end > beg) {
        float inv = 1.f / den;
        acc.x *= inv; acc.y *= inv;
    }
    out2[(size_t)orow * 32 + lane] = acc;
}

// ---------------- launch ----------------
extern "C" void kernel_launch(void* const* d_in, const int* in_sizes, int n_in,
                              void* d_out, int out_size)
{
    const float* feat_user = (const float*)d_in[0];
    const float* feat_item = (const float*)d_in[1];
    const float* W_user    = (const float*)d_in[2];
    const float* b_user    = (const float*)d_in[3];
    const float* W_item    = (const float*)d_in[4];
    const float* b_item    = (const float*)d_in[5];
    const float* attn_w    = (const float*)d_in[6];
    const int*   src_u2i   = (const int*)d_in[7];
    const int*   dst_u2i   = (const int*)d_in[8];
    const int*   src_i2u   = (const int*)d_in[9];
    const int*   dst_i2u   = (const int*)d_in[10];
    float* out = (float*)d_out;

    // true DEVICE addresses of __device__ globals (host-shadow/ATS trap!)
    float *Wh_user, *Wh_item, *su_src, *su_dst, *si_src, *si_dst;
    float2 *csr;
    int *cnt, *offs, *cursor, *bsum, *boff;
    cudaGetSymbolAddress((void**)&Wh_user, g_Wh_user);
    cudaGetSymbolAddress((void**)&Wh_item, g_Wh_item);
    cudaGetSymbolAddress((void**)&su_src,  g_su_src);
    cudaGetSymbolAddress((void**)&su_dst,  g_su_dst);
    cudaGetSymbolAddress((void**)&si_src,  g_si_src);
    cudaGetSymbolAddress((void**)&si_dst,  g_si_dst);
    cudaGetSymbolAddress((void**)&cnt,     g_cnt);
    cudaGetSymbolAddress((void**)&offs,    g_offs);
    cudaGetSymbolAddress((void**)&cursor,  g_cursor);
    cudaGetSymbolAddress((void**)&bsum,    g_bsum);
    cudaGetSymbolAddress((void**)&boff,    g_boff);
    cudaGetSymbolAddress((void**)&csr,     g_csr);

    zero_kernel<<<(N_NODE2 + 255) / 256, 256>>>(cnt);

    linear_attn_kernel<<<N_USER / LROWS, 256>>>(feat_user, W_user, b_user, attn_w,
                                                Wh_user, su_src, su_dst);
    linear_attn_kernel<<<N_ITEM / LROWS, 256>>>(feat_item, W_item, b_item, attn_w,
                                                Wh_item, si_src, si_dst);

    hist_kernel<<<(2 * (N_EDGE / 4) + 255) / 256, 256>>>(
        (const int4*)dst_u2i, (const int4*)dst_i2u, cnt);

    scan1_kernel<<<NBLK_SCAN, 256>>>(cnt, offs, bsum);
    scan2_kernel<<<1, 256>>>(bsum, boff);
    scan3_kernel<<<(N_NODE2 + 255) / 256, 256>>>(offs, boff, cursor);

    scatter_kernel<<<(N_EDGE2 + 255) / 256, 256>>>(
        src_u2i, dst_u2i, src_i2u, dst_i2u,
        su_src, su_dst, si_src, si_dst, cursor, csr);

    agg_kernel<<<(N_NODE2 * 32 + 255) / 256, 256>>>(offs, csr,
                                                    (const float2*)Wh_user,
                                                    (const float2*)Wh_item,
                                                    (float2*)out);
}

// round 7
// speedup vs baseline: 1.3390x; 1.3390x over previous
#include <cuda_runtime.h>

#define N_USER   100000
#define N_ITEM   100000
#define N_NODE2  200000          // combined dst space: [0,100K)=item(u2i), [100K,200K)=user(i2u)
#define N_EDGE   1600000
#define N_EDGE2  3200000
#define IN_DIM   128
#define OUT_DIM  64
#define NEG_SLOPE 0.01f
#define LROWS    32
#define NBLK_SCAN 196            // ceil(200000/1024)

// ---------------- device scratch (static, no runtime alloc) ----------------
__device__ float  g_Wh_user[(size_t)N_USER * OUT_DIM];   // 25.6 MB
__device__ float  g_Wh_item[(size_t)N_ITEM * OUT_DIM];   // 25.6 MB
__device__ float  g_su_src[N_USER];
__device__ float  g_su_dst[N_USER];
__device__ float  g_si_src[N_ITEM];
__device__ float  g_si_dst[N_ITEM];
__device__ int    g_cnt[N_NODE2];
__device__ int    g_offs[N_NODE2];
__device__ int    g_cursor[N_NODE2];
__device__ int    g_bsum[NBLK_SCAN];
__device__ int    g_boff[NBLK_SCAN];
__device__ float2 g_csr[N_EDGE2];     // packed (src_as_float, ex), 25.6 MB

// ---------------- per-replay reset: degree counters ----------------
__global__ __launch_bounds__(256) void zero_kernel(int* __restrict__ cnt)
{
    int i = blockIdx.x * blockDim.x + threadIdx.x;
    if (i < N_NODE2) cnt[i] = 0;
}

// ------- Wh = feat @ W + b fused with s_src/s_dst epilogue -------
// (round-5 measured-good tile: thread = 2 cols x 4 rows)
__global__ __launch_bounds__(256) void linear_attn_kernel(
    const float* __restrict__ feat, const float* __restrict__ W,
    const float* __restrict__ b, const float* __restrict__ attn,
    float* __restrict__ Wh, float* __restrict__ s_src, float* __restrict__ s_dst)
{
    __shared__ float Ws[IN_DIM * OUT_DIM];   // 32 KB
    __shared__ float fs[LROWS][IN_DIM];      // 16 KB (reused for Wh tile)
    int tid = threadIdx.x;

    #pragma unroll
    for (int i = tid; i < IN_DIM * OUT_DIM; i += 256) Ws[i] = W[i];

    int row0 = blockIdx.x * LROWS;
    const float4* fsrc = reinterpret_cast<const float4*>(feat + (size_t)row0 * IN_DIM);
    float4* fdst = reinterpret_cast<float4*>(&fs[0][0]);
    #pragma unroll
    for (int i = tid; i < LROWS * IN_DIM / 4; i += 256) fdst[i] = fsrc[i];
    __syncthreads();

    int cg = tid & 31;   // column pair index
    int rg = tid >> 5;   // row group (4 rows)
    const float2* Ws2 = reinterpret_cast<const float2*>(Ws);
    float2 acc[4] = {{0.f,0.f},{0.f,0.f},{0.f,0.f},{0.f,0.f}};

    #pragma unroll 8
    for (int k = 0; k < IN_DIM; k++) {
        float2 w = Ws2[k * 32 + cg];
        #pragma unroll
        for (int r = 0; r < 4; r++) {
            float f = fs[rg * 4 + r][k];
            acc[r].x = fmaf(f, w.x, acc[r].x);
            acc[r].y = fmaf(f, w.y, acc[r].y);
        }
    }

    float2 b2 = reinterpret_cast<const float2*>(b)[cg];
    __syncthreads();   // done reading fs; reuse as Wh tile
    float2* sWh2 = reinterpret_cast<float2*>(&fs[0][0]);   // [32][32] float2
    #pragma unroll
    for (int r = 0; r < 4; r++) {
        acc[r].x += b2.x; acc[r].y += b2.y;
        int row = rg * 4 + r;
        reinterpret_cast<float2*>(Wh)[(size_t)(row0 + row) * 32 + cg] = acc[r];
        sWh2[row * 32 + cg] = acc[r];
    }
    __syncthreads();

    // epilogue: 8 warps x 4 rows
    int wid = tid >> 5, lane = tid & 31;
    float a0 = attn[lane],      a1 = attn[lane + 32];
    float c0 = attn[64 + lane], c1 = attn[96 + lane];
    const float* sWh = &fs[0][0];
    #pragma unroll
    for (int rr = 0; rr < 4; rr++) {
        int row = wid * 4 + rr;
        float v0 = sWh[row * 64 + lane];
        float v1 = sWh[row * 64 + lane + 32];
        float ps = fmaf(v0, a0, v1 * a1);
        float pd = fmaf(v0, c0, v1 * c1);
        #pragma unroll
        for (int o = 16; o; o >>= 1) {
            ps += __shfl_xor_sync(0xffffffffu, ps, o);
            pd += __shfl_xor_sync(0xffffffffu, pd, o);
        }
        if (lane == 0) { s_src[row0 + row] = ps; s_dst[row0 + row] = pd; }
    }
}

// ---------------- histogram of dst degrees, both etypes (4 edges/thread) ----
__global__ __launch_bounds__(256) void hist_kernel(const int4* __restrict__ dstA4,
                                                   const int4* __restrict__ dstB4,
                                                   int* __restrict__ cnt)
{
    int i = blockIdx.x * blockDim.x + threadIdx.x;
    const int nq = N_EDGE / 4;
    if (i >= 2 * nq) return;
    bool second = i >= nq;
    int4 d = second ? dstB4[i - nq] : dstA4[i];
    int gbase = second ? N_ITEM : 0;
    atomicAdd(&cnt[gbase + d.x], 1);
    atomicAdd(&cnt[gbase + d.y], 1);
    atomicAdd(&cnt[gbase + d.z], 1);
    atomicAdd(&cnt[gbase + d.w], 1);
}

// ---------------- exclusive scan (3 kernels) ----------------
__global__ __launch_bounds__(256) void scan1_kernel(const int* __restrict__ cnt,
        int* __restrict__ offs, int* __restrict__ bsum)
{
    __shared__ int wsum[8];
    int tid = threadIdx.x;
    int base = blockIdx.x * 1024 + tid * 4;
    int v[4];
    #pragma unroll
    for (int q = 0; q < 4; q++) { int i = base + q; v[q] = (i < N_NODE2) ? cnt[i] : 0; }
    int t = v[0] + v[1] + v[2] + v[3];
    int lane = tid & 31, wid = tid >> 5;
    int inc = t;
    #pragma unroll
    for (int o = 1; o < 32; o <<= 1) { int n = __shfl_up_sync(0xffffffffu, inc, o); if (lane >= o) inc += n; }
    if (lane == 31) wsum[wid] = inc;
    __syncthreads();
    if (wid == 0) {
        int ws = (lane < 8) ? wsum[lane] : 0;
        int winc = ws;
        #pragma unroll
        for (int o = 1; o < 8; o <<= 1) { int n = __shfl_up_sync(0xffffffffu, winc, o); if (lane >= o) winc += n; }
        if (lane < 8) wsum[lane] = winc - ws;          // exclusive warp offsets
        if (lane == 7) bsum[blockIdx.x] = winc;        // block total
    }
    __syncthreads();
    int run = wsum[wid] + (inc - t);
    #pragma unroll
    for (int q = 0; q < 4; q++) { int i = base + q; if (i < N_NODE2) offs[i] = run; run += v[q]; }
}

__global__ __launch_bounds__(256) void scan2_kernel(const int* __restrict__ bsum,
                                                    int* __restrict__ boff)
{
    __shared__ int wsum[8];
    int tid = threadIdx.x;
    int v = (tid < NBLK_SCAN) ? bsum[tid] : 0;
    int lane = tid & 31, wid = tid >> 5;
    int inc = v;
    #pragma unroll
    for (int o = 1; o < 32; o <<= 1) { int n = __shfl_up_sync(0xffffffffu, inc, o); if (lane >= o) inc += n; }
    if (lane == 31) wsum[wid] = inc;
    __syncthreads();
    if (wid == 0) {
        int ws = (lane < 8) ? wsum[lane] : 0;
        int winc = ws;
        #pragma unroll
        for (int o = 1; o < 8; o <<= 1) { int n = __shfl_up_sync(0xffffffffu, winc, o); if (lane >= o) winc += n; }
        if (lane < 8) wsum[lane] = winc - ws;
    }
    __syncthreads();
    if (tid < NBLK_SCAN) boff[tid] = wsum[wid] + (inc - v);
}

__global__ __launch_bounds__(256) void scan3_kernel(int* __restrict__ offs,
        const int* __restrict__ boff, int* __restrict__ cursor)
{
    int i = blockIdx.x * blockDim.x + threadIdx.x;
    if (i >= N_NODE2) return;
    int o = offs[i] + boff[i >> 10];
    offs[i] = o;
    cursor[i] = o;
}

// --------- scatter (both etypes): ex = exp(lrelu(e)); csr[pos] = (src, ex) ---------
__global__ __launch_bounds__(256) void scatter_kernel(
    const int* __restrict__ srcA, const int* __restrict__ dstA,
    const int* __restrict__ srcB, const int* __restrict__ dstB,
    const float* __restrict__ su_src, const float* __restrict__ su_dst,
    const float* __restrict__ si_src, const float* __restrict__ si_dst,
    int* __restrict__ cursor, float2* __restrict__ csr)
{
    int t = blockIdx.x * blockDim.x + threadIdx.x;
    if (t >= N_EDGE2) return;
    bool second = t >= N_EDGE;
    int e = second ? t - N_EDGE : t;
    int s = second ? srcB[e] : srcA[e];
    int d = second ? dstB[e] : dstA[e];
    float vs = second ? si_src[s] : su_src[s];
    float vd = second ? su_dst[d] : si_dst[d];
    float v = vs + vd;
    v = v > 0.f ? v : NEG_SLOPE * v;
    float ex = __expf(v);
    int gd = (second ? N_ITEM : 0) + d;
    int pos = atomicAdd(&cursor[gd], 1);
    csr[pos] = make_float2(__int_as_float(s), ex);
}

// --------- aggregate: warp per dst node; fixed unroll-8 inner groups --------
// avg degree ~16: the inner loop MUST be compile-time unrollable or every edge
// becomes a dependent shfl->LDG chain. Padded lanes carry ex=0; the ej!=0
// predicate turns padding into predicated-off LDGs (no traffic, no branch).
__global__ __launch_bounds__(256) void agg_kernel(
    const int* __restrict__ offs, const float2* __restrict__ csr,
    const float2* __restrict__ Whu2, const float2* __restrict__ Whi2,
    float2* __restrict__ out2)
{
    int g = (blockIdx.x * 256 + threadIdx.x) >> 5;
    int lane = threadIdx.x & 31;
    if (g >= N_NODE2) return;

    int beg = offs[g];
    int end = (g == N_NODE2 - 1) ? N_EDGE2 : offs[g + 1];
    const float2* Wh2 = (g < N_ITEM) ? Whu2 : Whi2;            // item-dst <- user src
    int orow = (g < N_ITEM) ? (N_USER + g) : (g - N_ITEM);

    float2 acc = make_float2(0.f, 0.f);
    float den = 0.f;

    for (int k0 = beg; k0 < end; k0 += 32) {
        int k = k0 + lane;
        float2 p = (k < end) ? csr[k] : make_float2(0.f, 0.f);  // pad: s=0(valid), ex=0
        int   s  = __float_as_int(p.x);
        float ex = p.y;
        int m = end - k0; if (m > 32) m = 32;
        for (int j0 = 0; j0 < m; j0 += 8) {
            #pragma unroll
            for (int jj = 0; jj < 8; jj++) {
                int   sj = __shfl_sync(0xffffffffu, s,  j0 + jj);
                float ej = __shfl_sync(0xffffffffu, ex, j0 + jj);
                if (ej != 0.f) {
                    float2 z = Wh2[(size_t)sj * 32 + lane];
                    acc.x = fmaf(ej, z.x, acc.x);
                    acc.y = fmaf(ej, z.y, acc.y);
                    den += ej;
                }
            }
        }
    }
    if (end > beg) {
        float inv = 1.f / den;
        acc.x *= inv; acc.y *= inv;
    }
    out2[(size_t)orow * 32 + lane] = acc;
}

// ---------------- launch ----------------
extern "C" void kernel_launch(void* const* d_in, const int* in_sizes, int n_in,
                              void* d_out, int out_size)
{
    const float* feat_user = (const float*)d_in[0];
    const float* feat_item = (const float*)d_in[1];
    const float* W_user    = (const float*)d_in[2];
    const float* b_user    = (const float*)d_in[3];
    const float* W_item    = (const float*)d_in[4];
    const float* b_item    = (const float*)d_in[5];
    const float* attn_w    = (const float*)d_in[6];
    const int*   src_u2i   = (const int*)d_in[7];
    const int*   dst_u2i   = (const int*)d_in[8];
    const int*   src_i2u   = (const int*)d_in[9];
    const int*   dst_i2u   = (const int*)d_in[10];
    float* out = (float*)d_out;

    // true DEVICE addresses of __device__ globals (host-shadow/ATS trap!)
    float *Wh_user, *Wh_item, *su_src, *su_dst, *si_src, *si_dst;
    float2 *csr;
    int *cnt, *offs, *cursor, *bsum, *boff;
    cudaGetSymbolAddress((void**)&Wh_user, g_Wh_user);
    cudaGetSymbolAddress((void**)&Wh_item, g_Wh_item);
    cudaGetSymbolAddress((void**)&su_src,  g_su_src);
    cudaGetSymbolAddress((void**)&su_dst,  g_su_dst);
    cudaGetSymbolAddress((void**)&si_src,  g_si_src);
    cudaGetSymbolAddress((void**)&si_dst,  g_si_dst);
    cudaGetSymbolAddress((void**)&cnt,     g_cnt);
    cudaGetSymbolAddress((void**)&offs,    g_offs);
    cudaGetSymbolAddress((void**)&cursor,  g_cursor);
    cudaGetSymbolAddress((void**)&bsum,    g_bsum);
    cudaGetSymbolAddress((void**)&boff,    g_boff);
    cudaGetSymbolAddress((void**)&csr,     g_csr);

    zero_kernel<<<(N_NODE2 + 255) / 256, 256>>>(cnt);

    linear_attn_kernel<<<N_USER / LROWS, 256>>>(feat_user, W_user, b_user, attn_w,
                                                Wh_user, su_src, su_dst);
    linear_attn_kernel<<<N_ITEM / LROWS, 256>>>(feat_item, W_item, b_item, attn_w,
                                                Wh_item, si_src, si_dst);

    hist_kernel<<<(2 * (N_EDGE / 4) + 255) / 256, 256>>>(
        (const int4*)dst_u2i, (const int4*)dst_i2u, cnt);

    scan1_kernel<<<NBLK_SCAN, 256>>>(cnt, offs, bsum);
    scan2_kernel<<<1, 256>>>(bsum, boff);
    scan3_kernel<<<(N_NODE2 + 255) / 256, 256>>>(offs, boff, cursor);

    scatter_kernel<<<(N_EDGE2 + 255) / 256, 256>>>(
        src_u2i, dst_u2i, src_i2u, dst_i2u,
        su_src, su_dst, si_src, si_dst, cursor, csr);

    agg_kernel<<<(N_NODE2 * 32 + 255) / 256, 256>>>(offs, csr,
                                                    (const float2*)Wh_user,
                                                    (const float2*)Wh_item,
                                                    (float2*)out);
}